// round 6
// baseline (speedup 1.0000x reference)
#include <cuda_runtime.h>
#include <cuda_fp16.h>
#include <math.h>
#include <stdint.h>

// ---------------- problem constants ----------------
#define R_RAYS      4096
#define S_SAMPLES   32
#define RS_TOTAL    131072
#define M_SAMPLES   6
#define NUM_LEVELS  10
#define FEAT_DIM    40
#define HASHMASK    2097151u
#define RGB_ELEMS   393216

#define ROWS_CTA    64
#define NCTA        (RS_TOTAL / ROWS_CTA)     // 2048

__constant__ int c_offsets[NUM_LEVELS] = {
    0, 4920, 40864, 315496, 2412648, 4509800, 6606952, 8704104, 10801256, 12898408
};
__constant__ int c_sizes[NUM_LEVELS] = {
    4920, 35944, 274632, 2097152, 2097152, 2097152, 2097152, 2097152, 2097152, 2097152
};

// packed fp16 weight fragments (layout documented in prep_kernel)
#define PK_TOTAL_H2 116224
__device__ __align__(16) __half2 Wpk[PK_TOTAL_H2];

#define SLAB 568   // slab row stride in halves

// ---------------- mma helper ----------------
__device__ __forceinline__ void mma16816(float c[4],
    unsigned a0, unsigned a1, unsigned a2, unsigned a3,
    unsigned b0, unsigned b1)
{
    asm volatile(
        "mma.sync.aligned.m16n8k16.row.col.f32.f16.f16.f32 "
        "{%0,%1,%2,%3}, {%4,%5,%6,%7}, {%8,%9}, {%0,%1,%2,%3};"
        : "+f"(c[0]), "+f"(c[1]), "+f"(c[2]), "+f"(c[3])
        : "r"(a0), "r"(a1), "r"(a2), "r"(a3), "r"(b0), "r"(b1));
}

// ---------------- kernel 0: weight prep ----------------
__global__ __launch_bounds__(256) void prep_kernel(
    const float* __restrict__ dw1, const float* __restrict__ dw2,
    const float* __restrict__ vw0, const float* __restrict__ vw1)
{
    int idx = blockIdx.x * 256 + threadIdx.x;
    if (idx >= PK_TOTAL_H2) return;

    int local, NP, layer;
    if (idx < 1536)        { layer = 1; local = idx;         NP = 4;  }
    else if (idx < 9728)   { layer = 2; local = idx - 1536;  NP = 16; }
    else if (idx < 46592)  { layer = 3; local = idx - 9728;  NP = 16; }
    else                   { layer = 4; local = idx - 46592; NP = 16; }

    const int j    = local & 3;
    const int lane = (local >> 2) & 31;
    const int rem  = local >> 7;
    const int np   = rem % NP;
    const int kt   = rem / NP;

    const int nt  = np * 2 + (j >> 1);
    const int reg = j & 1;
    const int n   = nt * 8 + (lane >> 2);
    const int k   = kt * 16 + reg * 8 + (lane & 3) * 2;

    float v0 = 0.f, v1 = 0.f;
    if (layer == 1) {
        if (k     < 40) v0 = dw1[k * 64 + n];
        if (k + 1 < 40) v1 = dw1[(k + 1) * 64 + n];
    } else if (layer == 2) {
        v0 = dw2[k * 256 + n];
        v1 = dw2[(k + 1) * 256 + n];
    } else if (layer == 3) {
        if (k     < 283) v0 = vw0[k * 256 + n];
        if (k + 1 < 283) v1 = vw0[(k + 1) * 256 + n];
    } else {
        if (k     < 539) v0 = vw1[k * 256 + n];
        if (k + 1 < 539) v1 = vw1[(k + 1) * 256 + n];
    }
    Wpk[idx] = __floats2half2_rn(v0, v1);
}

// ---------------- generic fragment-GEMM layer over the smem slab ----------------
template<int KT, int NTW, int NP>
__device__ __forceinline__ void run_layer(
    const __half* slab, int acol0, int mr, int gr, int gc,
    const __half2* __restrict__ wpk, int nh, int lane, float C[][4])
{
    const __half* arow = slab + (mr + gr) * SLAB + acol0 + gc * 2;
    const uint4* wbase = (const uint4*)wpk + (size_t)(nh * (NP / 2)) * 32 + lane;
    #pragma unroll 1
    for (int kt = 0; kt < KT; kt++) {
        const __half* ap = arow + kt * 16;
        unsigned a0 = *(const unsigned*)(ap);
        unsigned a2 = *(const unsigned*)(ap + 8);
        unsigned a1 = *(const unsigned*)(ap + 8 * SLAB);
        unsigned a3 = *(const unsigned*)(ap + 8 * SLAB + 8);
        const uint4* wp = wbase + (size_t)kt * NP * 32;
        #pragma unroll
        for (int p = 0; p < NTW / 2; p++) {
            uint4 b = __ldg(wp + p * 32);
            mma16816(C[2 * p],     a0, a1, a2, a3, b.x, b.y);
            mma16816(C[2 * p + 1], a0, a1, a2, a3, b.z, b.w);
        }
    }
}

// ---------------- fused kernel: encode (64 rows x 10 levels) + MLP ----------------
// smem: slab 64x568 halves (72704B) | dirsm 64f | rwsm 768f | parth 64*6f
#define SM_DIR   72704
#define SM_RW    72960
#define SM_PARTH 76032
#define SM_TOTAL 77568

__global__ __launch_bounds__(256, 2) void fused_kernel(
    const float* __restrict__ means,
    const float* __restrict__ stds,
    const float4* __restrict__ table,
    const float* __restrict__ vd,
    const float* __restrict__ db1, const float* __restrict__ db2,
    const float* __restrict__ vb0, const float* __restrict__ vb1,
    const float* __restrict__ rw,  const float* __restrict__ rbias,
    float* __restrict__ out)
{
    extern __shared__ char dyn[];
    __half* slab = (__half*)dyn;
    float* dirsm = (float*)(dyn + SM_DIR);
    float* rwsm  = (float*)(dyn + SM_RW);
    float* parth = (float*)(dyn + SM_PARTH);

    const int t = threadIdx.x;
    const int w = t >> 5, lane = t & 31;
    const int gr = lane >> 2, gc = lane & 3;
    const int mt = w & 3, nh = w >> 2;      // 4 m-tiles x 2 n-halves
    const int mr = mt * 16;
    const int rs0 = blockIdx.x * ROWS_CTA;

    // rw -> smem
    for (int i = t; i < 768; i += 256) rwsm[i] = rw[i];

    // dir encoding: 2 rays x 32 cols (cols >= 27 zero)
    if (t < 64) {
        int ray = t >> 5, c = t & 31;
        int rg = blockIdx.x * 2 + ray;
        float v = 0.f;
        if (c < 3) v = vd[rg * 3 + c];
        else if (c < 15) { int j = c - 3;  v = sinf(vd[rg * 3 + (j % 3)] * (float)(1 << (j / 3))); }
        else if (c < 27) { int j = c - 15; v = cosf(vd[rg * 3 + (j % 3)] * (float)(1 << (j / 3))); }
        dirsm[t] = v;
        // zero feat pad cols 40..47
        *(uint4*)&slab[t * SLAB + 40] = make_uint4(0, 0, 0, 0);
    }

    // ---- hash-grid encode: 640 (row, level) tasks over 256 threads ----
    #pragma unroll 1
    for (int i = t; i < ROWS_CTA * NUM_LEVELS; i += 256) {
        const int level = i >> 6;
        const int r = i & 63;
        const int rs = rs0 + r;

        const float scale = (float)(16 << level);
        const unsigned res = (unsigned)((16 << level) + 1);
        const bool dense = (level < 3);
        const int off = c_offsets[level];
        const unsigned size_m1 = (unsigned)(c_sizes[level] - 1);

        float acc0 = 0.f, acc1 = 0.f, acc2 = 0.f, acc3 = 0.f;

        #pragma unroll 2
        for (int m = 0; m < M_SAMPLES; m++) {
            const int pidx = rs * M_SAMPLES + m;
            const float mx = means[pidx * 3 + 0];
            const float my = means[pidx * 3 + 1];
            const float mz = means[pidx * 3 + 2];
            const float sd = stds[pidx];
            const float wl = erff(1.0f / (2.8284271247461903f * sd * scale));

            float px = (mx + 1.0f) * 0.5f * scale + 0.5f;
            float py = (my + 1.0f) * 0.5f * scale + 0.5f;
            float pz = (mz + 1.0f) * 0.5f * scale + 0.5f;
            float f0x = floorf(px), f0y = floorf(py), f0z = floorf(pz);
            float fx = px - f0x, fy = py - f0y, fz = pz - f0z;
            unsigned ux = (unsigned)f0x, uy = (unsigned)f0y, uz = (unsigned)f0z;

            #pragma unroll
            for (int c = 0; c < 8; c++) {
                const unsigned bx = c & 1u, by = (c >> 1) & 1u, bz = (c >> 2) & 1u;
                const unsigned cx = ux + bx, cy = uy + by, cz = uz + bz;
                unsigned idx;
                if (dense) { idx = (cx * res + cy) * res + cz; idx = min(idx, size_m1); }
                else { idx = (cx * 1u) ^ (cy * 2654435761u) ^ (cz * 805459861u); idx &= HASHMASK; }
                const float wx = bx ? fx : (1.0f - fx);
                const float wy = by ? fy : (1.0f - fy);
                const float wz = bz ? fz : (1.0f - fz);
                const float wgt = wx * wy * wz * wl;
                const float4 tt = __ldg(table + off + (int)idx);
                acc0 += wgt * tt.x; acc1 += wgt * tt.y; acc2 += wgt * tt.z; acc3 += wgt * tt.w;
            }
        }
        const float inv = 1.0f / 6.0f;
        __half2 lo = __floats2half2_rn(acc0 * inv, acc1 * inv);
        __half2 hi = __floats2half2_rn(acc2 * inv, acc3 * inv);
        *(__half2*)&slab[r * SLAB + level * 4]     = lo;
        *(__half2*)&slab[r * SLAB + level * 4 + 2] = hi;
    }
    __syncthreads();

    // dir -> slab cols 512..543
    {
        int r = t >> 2, c0 = (t & 3) * 8;
        const float* ds = &dirsm[(r >> 5) * 32];
        #pragma unroll
        for (int j = 0; j < 8; j++)
            slab[r * SLAB + 512 + c0 + j] = __float2half_rn(ds[c0 + j]);
    }
    __syncthreads();

    // ---- L1: feat(cols 0..47) @ W1 -> h1 (relu) -> cols 64..127 ----
    {
        float C[4][4] = {};
        run_layer<3, 4, 4>(slab, 0, mr, gr, gc, Wpk, nh, lane, C);
        #pragma unroll
        for (int nt = 0; nt < 4; nt++) {
            int n = nh * 32 + nt * 8 + 2 * gc;
            float2 b = *(const float2*)&db1[n];
            __half2 lo = __floats2half2_rn(fmaxf(C[nt][0] + b.x, 0.f), fmaxf(C[nt][1] + b.y, 0.f));
            __half2 hi = __floats2half2_rn(fmaxf(C[nt][2] + b.x, 0.f), fmaxf(C[nt][3] + b.y, 0.f));
            *(__half2*)&slab[(mr + gr) * SLAB + 64 + n]     = lo;
            *(__half2*)&slab[(mr + gr + 8) * SLAB + 64 + n] = hi;
        }
    }
    __syncthreads();

    // ---- L2: h1 @ W2 -> x (cols 256..511); density ----
    {
        float C[16][4] = {};
        run_layer<4, 16, 16>(slab, 64, mr, gr, gc, Wpk + 1536, nh, lane, C);
        if (nh == 0 && gc == 0) {
            float xa = C[0][0] + __ldg(&db2[0]) - 1.0f;
            float xb = C[0][2] + __ldg(&db2[0]) - 1.0f;
            out[RGB_ELEMS + rs0 + mr + gr]     = fmaxf(xa, 0.f) + log1pf(expf(-fabsf(xa)));
            out[RGB_ELEMS + rs0 + mr + gr + 8] = fmaxf(xb, 0.f) + log1pf(expf(-fabsf(xb)));
        }
        #pragma unroll
        for (int nt = 0; nt < 16; nt++) {
            int n = nh * 128 + nt * 8 + 2 * gc;
            float2 b = *(const float2*)&db2[n];
            __half2 lo = __floats2half2_rn(C[nt][0] + b.x, C[nt][1] + b.y);
            __half2 hi = __floats2half2_rn(C[nt][2] + b.x, C[nt][3] + b.y);
            *(__half2*)&slab[(mr + gr) * SLAB + 256 + n]     = lo;
            *(__half2*)&slab[(mr + gr + 8) * SLAB + 256 + n] = hi;
        }
    }
    __syncthreads();

    // ---- L3: [x|dir](cols 256..543) @ W3 -> h2 (relu) -> cols 0..255 ----
    {
        float C[16][4] = {};
        run_layer<18, 16, 16>(slab, 256, mr, gr, gc, Wpk + 9728, nh, lane, C);
        #pragma unroll
        for (int nt = 0; nt < 16; nt++) {
            int n = nh * 128 + nt * 8 + 2 * gc;
            float2 b = *(const float2*)&vb0[n];
            __half2 lo = __floats2half2_rn(fmaxf(C[nt][0] + b.x, 0.f), fmaxf(C[nt][1] + b.y, 0.f));
            __half2 hi = __floats2half2_rn(fmaxf(C[nt][2] + b.x, 0.f), fmaxf(C[nt][3] + b.y, 0.f));
            *(__half2*)&slab[(mr + gr) * SLAB + n]     = lo;
            *(__half2*)&slab[(mr + gr + 8) * SLAB + n] = hi;
        }
    }
    __syncthreads();

    // ---- L4: [h2|x|dir](cols 0..543) @ W4 -> h3 (regs) -> rgb head ----
    {
        float C[16][4] = {};
        run_layer<34, 16, 16>(slab, 0, mr, gr, gc, Wpk + 46592, nh, lane, C);

        float pl[3] = {0.f, 0.f, 0.f}, ph[3] = {0.f, 0.f, 0.f};
        #pragma unroll
        for (int nt = 0; nt < 16; nt++) {
            int n = nh * 128 + nt * 8 + 2 * gc;
            float2 b = *(const float2*)&vb1[n];
            float h0 = fmaxf(C[nt][0] + b.x, 0.f);
            float h1 = fmaxf(C[nt][1] + b.y, 0.f);
            float h2 = fmaxf(C[nt][2] + b.x, 0.f);
            float h3 = fmaxf(C[nt][3] + b.y, 0.f);
            #pragma unroll
            for (int j = 0; j < 3; j++) {
                pl[j] += h0 * rwsm[n * 3 + j] + h1 * rwsm[(n + 1) * 3 + j];
                ph[j] += h2 * rwsm[n * 3 + j] + h3 * rwsm[(n + 1) * 3 + j];
            }
        }
        #pragma unroll
        for (int j = 0; j < 3; j++) {
            pl[j] += __shfl_xor_sync(0xffffffffu, pl[j], 1);
            pl[j] += __shfl_xor_sync(0xffffffffu, pl[j], 2);
            ph[j] += __shfl_xor_sync(0xffffffffu, ph[j], 1);
            ph[j] += __shfl_xor_sync(0xffffffffu, ph[j], 2);
        }
        if (gc == 0) {
            #pragma unroll
            for (int j = 0; j < 3; j++) {
                parth[(mr + gr) * 6 + nh * 3 + j]     = pl[j];
                parth[(mr + gr + 8) * 6 + nh * 3 + j] = ph[j];
            }
        }
    }
    __syncthreads();

    if (t < ROWS_CTA) {
        #pragma unroll
        for (int j = 0; j < 3; j++) {
            float s = parth[t * 6 + j] + parth[t * 6 + 3 + j] + __ldg(&rbias[j]);
            float sig = 1.0f / (1.0f + expf(-s));
            out[(rs0 + t) * 3 + j] = sig * 1.002f - 0.001f;
        }
    }
}

// ---------------- launch ----------------
extern "C" void kernel_launch(void* const* d_in, const int* in_sizes, int n_in,
                              void* d_out, int out_size)
{
    const float* means = (const float*)d_in[0];
    const float* stds  = (const float*)d_in[1];
    const float* vd    = (const float*)d_in[2];
    const float* table = (const float*)d_in[3];
    const float* dw1   = (const float*)d_in[4];
    const float* db1   = (const float*)d_in[5];
    const float* dw2   = (const float*)d_in[6];
    const float* db2   = (const float*)d_in[7];
    const float* vw0   = (const float*)d_in[8];
    const float* vb0   = (const float*)d_in[9];
    const float* vw1   = (const float*)d_in[10];
    const float* vb1   = (const float*)d_in[11];
    const float* rw    = (const float*)d_in[12];
    const float* rb    = (const float*)d_in[13];
    float* out = (float*)d_out;

    cudaFuncSetAttribute(fused_kernel, cudaFuncAttributeMaxDynamicSharedMemorySize, SM_TOTAL);

    prep_kernel<<<(PK_TOTAL_H2 + 255) / 256, 256>>>(dw1, dw2, vw0, vw1);

    fused_kernel<<<NCTA, 256, SM_TOTAL>>>(means, stds, (const float4*)table, vd,
                                          db1, db2, vb0, vb1, rw, rb, out);
}

// round 7
// speedup vs baseline: 1.4930x; 1.4930x over previous
#include <cuda_runtime.h>
#include <cuda_fp16.h>
#include <math.h>
#include <stdint.h>

// ---------------- problem constants ----------------
#define R_RAYS      4096
#define S_SAMPLES   32
#define RS_TOTAL    131072
#define M_SAMPLES   6
#define NUM_LEVELS  10
#define FEAT_DIM    40
#define HASHMASK    2097151u
#define RGB_ELEMS   393216

#define ROWS_CTA    64
#define NCTA        (RS_TOTAL / ROWS_CTA)     // 2048

__constant__ int c_offsets[NUM_LEVELS] = {
    0, 4920, 40864, 315496, 2412648, 4509800, 6606952, 8704104, 10801256, 12898408
};
__constant__ int c_sizes[NUM_LEVELS] = {
    4920, 35944, 274632, 2097152, 2097152, 2097152, 2097152, 2097152, 2097152, 2097152
};

// fp16 feature scratch: [rs][40]
__device__ __half g_feat_h[RS_TOTAL * FEAT_DIM];

// packed fp16 weight fragments (layout documented in prep_kernel)
#define PK_TOTAL_H2 116224
__device__ __align__(16) __half2 Wpk[PK_TOTAL_H2];

#define SLAB 568   // slab row stride in halves

// ---------------- mma helper ----------------
__device__ __forceinline__ void mma16816(float c[4],
    unsigned a0, unsigned a1, unsigned a2, unsigned a3,
    unsigned b0, unsigned b1)
{
    asm volatile(
        "mma.sync.aligned.m16n8k16.row.col.f32.f16.f16.f32 "
        "{%0,%1,%2,%3}, {%4,%5,%6,%7}, {%8,%9}, {%0,%1,%2,%3};"
        : "+f"(c[0]), "+f"(c[1]), "+f"(c[2]), "+f"(c[3])
        : "r"(a0), "r"(a1), "r"(a2), "r"(a3), "r"(b0), "r"(b1));
}

// ---------------- kernel 0: weight prep ----------------
__global__ __launch_bounds__(256) void prep_kernel(
    const float* __restrict__ dw1, const float* __restrict__ dw2,
    const float* __restrict__ vw0, const float* __restrict__ vw1)
{
    int idx = blockIdx.x * 256 + threadIdx.x;
    if (idx >= PK_TOTAL_H2) return;

    int local, NP, layer;
    if (idx < 1536)        { layer = 1; local = idx;         NP = 4;  }
    else if (idx < 9728)   { layer = 2; local = idx - 1536;  NP = 16; }
    else if (idx < 46592)  { layer = 3; local = idx - 9728;  NP = 16; }
    else                   { layer = 4; local = idx - 46592; NP = 16; }

    const int j    = local & 3;
    const int lane = (local >> 2) & 31;
    const int rem  = local >> 7;
    const int np   = rem % NP;
    const int kt   = rem / NP;

    const int nt  = np * 2 + (j >> 1);
    const int reg = j & 1;
    const int n   = nt * 8 + (lane >> 2);
    const int k   = kt * 16 + reg * 8 + (lane & 3) * 2;

    float v0 = 0.f, v1 = 0.f;
    if (layer == 1) {
        if (k     < 40) v0 = dw1[k * 64 + n];
        if (k + 1 < 40) v1 = dw1[(k + 1) * 64 + n];
    } else if (layer == 2) {
        v0 = dw2[k * 256 + n];
        v1 = dw2[(k + 1) * 256 + n];
    } else if (layer == 3) {
        if (k     < 283) v0 = vw0[k * 256 + n];
        if (k + 1 < 283) v1 = vw0[(k + 1) * 256 + n];
    } else {
        if (k     < 539) v0 = vw1[k * 256 + n];
        if (k + 1 < 539) v1 = vw1[(k + 1) * 256 + n];
    }
    Wpk[idx] = __floats2half2_rn(v0, v1);
}

// ---------------- kernel 1: hash-grid encode (full m-unroll, fp16 out) ----------------
__global__ __launch_bounds__(128) void grid_encode_kernel(
    const float* __restrict__ means,
    const float* __restrict__ stds,
    const float4* __restrict__ table)
{
    int rs = blockIdx.x * blockDim.x + threadIdx.x;
    int level = blockIdx.y;

    const float scale = (float)(16 << level);
    const unsigned res = (unsigned)((16 << level) + 1);
    const bool dense = (level < 3);
    const int off = c_offsets[level];
    const unsigned size_m1 = (unsigned)(c_sizes[level] - 1);

    float acc0 = 0.f, acc1 = 0.f, acc2 = 0.f, acc3 = 0.f;

    #pragma unroll
    for (int m = 0; m < M_SAMPLES; m++) {
        const int pidx = rs * M_SAMPLES + m;
        const float mx = means[pidx * 3 + 0];
        const float my = means[pidx * 3 + 1];
        const float mz = means[pidx * 3 + 2];
        const float sd = stds[pidx];
        const float wl = erff(1.0f / (2.8284271247461903f * sd * scale));

        float px = (mx + 1.0f) * 0.5f * scale + 0.5f;
        float py = (my + 1.0f) * 0.5f * scale + 0.5f;
        float pz = (mz + 1.0f) * 0.5f * scale + 0.5f;
        float f0x = floorf(px), f0y = floorf(py), f0z = floorf(pz);
        float fx = px - f0x, fy = py - f0y, fz = pz - f0z;
        unsigned ux = (unsigned)f0x, uy = (unsigned)f0y, uz = (unsigned)f0z;

        #pragma unroll
        for (int c = 0; c < 8; c++) {
            const unsigned bx = c & 1u, by = (c >> 1) & 1u, bz = (c >> 2) & 1u;
            const unsigned cx = ux + bx, cy = uy + by, cz = uz + bz;
            unsigned idx;
            if (dense) { idx = (cx * res + cy) * res + cz; idx = min(idx, size_m1); }
            else { idx = (cx * 1u) ^ (cy * 2654435761u) ^ (cz * 805459861u); idx &= HASHMASK; }
            const float wx = bx ? fx : (1.0f - fx);
            const float wy = by ? fy : (1.0f - fy);
            const float wz = bz ? fz : (1.0f - fz);
            const float w = wx * wy * wz * wl;
            const float4 tt = __ldg(table + off + (int)idx);
            acc0 += w * tt.x; acc1 += w * tt.y; acc2 += w * tt.z; acc3 += w * tt.w;
        }
    }
    const float inv = 1.0f / 6.0f;
    __half2 lo = __floats2half2_rn(acc0 * inv, acc1 * inv);
    __half2 hi = __floats2half2_rn(acc2 * inv, acc3 * inv);
    // 8B store: [rs][level*4 .. level*4+3]
    *(__half2*)&g_feat_h[rs * FEAT_DIM + level * 4]     = lo;
    *(__half2*)&g_feat_h[rs * FEAT_DIM + level * 4 + 2] = hi;
}

// ---------------- generic fragment-GEMM layer over the smem slab ----------------
template<int KT, int NTW, int NP>
__device__ __forceinline__ void run_layer(
    const __half* slab, int acol0, int mr, int gr, int gc,
    const __half2* __restrict__ wpk, int nh, int lane, float C[][4])
{
    const __half* arow = slab + (mr + gr) * SLAB + acol0 + gc * 2;
    const uint4* wbase = (const uint4*)wpk + (size_t)(nh * (NP / 2)) * 32 + lane;
    #pragma unroll 1
    for (int kt = 0; kt < KT; kt++) {
        const __half* ap = arow + kt * 16;
        unsigned a0 = *(const unsigned*)(ap);
        unsigned a2 = *(const unsigned*)(ap + 8);
        unsigned a1 = *(const unsigned*)(ap + 8 * SLAB);
        unsigned a3 = *(const unsigned*)(ap + 8 * SLAB + 8);
        const uint4* wp = wbase + (size_t)kt * NP * 32;
        #pragma unroll
        for (int p = 0; p < NTW / 2; p++) {
            uint4 b = __ldg(wp + p * 32);
            mma16816(C[2 * p],     a0, a1, a2, a3, b.x, b.y);
            mma16816(C[2 * p + 1], a0, a1, a2, a3, b.z, b.w);
        }
    }
}

// ---------------- kernel 2: MLP, 64 rows/CTA, occ 2 ----------------
// smem: slab 64x568 halves (72704B) | dirsm 64f | rwsm 768f | parth 64*6f
#define SM_DIR   72704
#define SM_RW    72960
#define SM_PARTH 76032
#define SM_TOTAL 77568

__global__ __launch_bounds__(256, 2) void mlp_mma_kernel(
    const float* __restrict__ vd,
    const float* __restrict__ db1, const float* __restrict__ db2,
    const float* __restrict__ vb0, const float* __restrict__ vb1,
    const float* __restrict__ rw,  const float* __restrict__ rbias,
    float* __restrict__ out)
{
    extern __shared__ char dyn[];
    __half* slab = (__half*)dyn;
    float* dirsm = (float*)(dyn + SM_DIR);
    float* rwsm  = (float*)(dyn + SM_RW);
    float* parth = (float*)(dyn + SM_PARTH);

    const int t = threadIdx.x;
    const int w = t >> 5, lane = t & 31;
    const int gr = lane >> 2, gc = lane & 3;
    const int mt = w & 3, nh = w >> 2;      // 4 m-tiles x 2 n-halves
    const int mr = mt * 16;
    const int rs0 = blockIdx.x * ROWS_CTA;

    // rw -> smem
    for (int i = t; i < 768; i += 256) rwsm[i] = rw[i];

    // dir encoding: 2 rays x 32 cols (cols >= 27 zero)
    if (t < 64) {
        int ray = t >> 5, c = t & 31;
        int rg = blockIdx.x * 2 + ray;
        float v = 0.f;
        if (c < 3) v = vd[rg * 3 + c];
        else if (c < 15) { int j = c - 3;  v = sinf(vd[rg * 3 + (j % 3)] * (float)(1 << (j / 3))); }
        else if (c < 27) { int j = c - 15; v = cosf(vd[rg * 3 + (j % 3)] * (float)(1 << (j / 3))); }
        dirsm[t] = v;
        // zero feat pad cols 40..47
        *(uint4*)&slab[t * SLAB + 40] = make_uint4(0, 0, 0, 0);
    }

    // feat (fp16) -> slab cols 0..39 : 64 rows x 20 uint copies
    #pragma unroll
    for (int i = t; i < ROWS_CTA * 20; i += 256) {
        int r = i / 20, c = i % 20;
        *(unsigned*)&slab[r * SLAB + c * 2] =
            *(const unsigned*)&g_feat_h[(rs0 + r) * FEAT_DIM + c * 2];
    }
    __syncthreads();

    // dir -> slab cols 512..543
    {
        int r = t >> 2, c0 = (t & 3) * 8;
        const float* ds = &dirsm[(r >> 5) * 32];
        #pragma unroll
        for (int j = 0; j < 8; j++)
            slab[r * SLAB + 512 + c0 + j] = __float2half_rn(ds[c0 + j]);
    }
    __syncthreads();

    // ---- L1: feat(cols 0..47) @ W1 -> h1 (relu) -> cols 64..127 ----
    {
        float C[4][4] = {};
        run_layer<3, 4, 4>(slab, 0, mr, gr, gc, Wpk, nh, lane, C);
        #pragma unroll
        for (int nt = 0; nt < 4; nt++) {
            int n = nh * 32 + nt * 8 + 2 * gc;
            float2 b = *(const float2*)&db1[n];
            __half2 lo = __floats2half2_rn(fmaxf(C[nt][0] + b.x, 0.f), fmaxf(C[nt][1] + b.y, 0.f));
            __half2 hi = __floats2half2_rn(fmaxf(C[nt][2] + b.x, 0.f), fmaxf(C[nt][3] + b.y, 0.f));
            *(__half2*)&slab[(mr + gr) * SLAB + 64 + n]     = lo;
            *(__half2*)&slab[(mr + gr + 8) * SLAB + 64 + n] = hi;
        }
    }
    __syncthreads();

    // ---- L2: h1 @ W2 -> x (cols 256..511); density ----
    {
        float C[16][4] = {};
        run_layer<4, 16, 16>(slab, 64, mr, gr, gc, Wpk + 1536, nh, lane, C);
        if (nh == 0 && gc == 0) {
            float xa = C[0][0] + __ldg(&db2[0]) - 1.0f;
            float xb = C[0][2] + __ldg(&db2[0]) - 1.0f;
            out[RGB_ELEMS + rs0 + mr + gr]     = fmaxf(xa, 0.f) + log1pf(expf(-fabsf(xa)));
            out[RGB_ELEMS + rs0 + mr + gr + 8] = fmaxf(xb, 0.f) + log1pf(expf(-fabsf(xb)));
        }
        #pragma unroll
        for (int nt = 0; nt < 16; nt++) {
            int n = nh * 128 + nt * 8 + 2 * gc;
            float2 b = *(const float2*)&db2[n];
            __half2 lo = __floats2half2_rn(C[nt][0] + b.x, C[nt][1] + b.y);
            __half2 hi = __floats2half2_rn(C[nt][2] + b.x, C[nt][3] + b.y);
            *(__half2*)&slab[(mr + gr) * SLAB + 256 + n]     = lo;
            *(__half2*)&slab[(mr + gr + 8) * SLAB + 256 + n] = hi;
        }
    }
    __syncthreads();

    // ---- L3: [x|dir](cols 256..543) @ W3 -> h2 (relu) -> cols 0..255 ----
    {
        float C[16][4] = {};
        run_layer<18, 16, 16>(slab, 256, mr, gr, gc, Wpk + 9728, nh, lane, C);
        #pragma unroll
        for (int nt = 0; nt < 16; nt++) {
            int n = nh * 128 + nt * 8 + 2 * gc;
            float2 b = *(const float2*)&vb0[n];
            __half2 lo = __floats2half2_rn(fmaxf(C[nt][0] + b.x, 0.f), fmaxf(C[nt][1] + b.y, 0.f));
            __half2 hi = __floats2half2_rn(fmaxf(C[nt][2] + b.x, 0.f), fmaxf(C[nt][3] + b.y, 0.f));
            *(__half2*)&slab[(mr + gr) * SLAB + n]     = lo;
            *(__half2*)&slab[(mr + gr + 8) * SLAB + n] = hi;
        }
    }
    __syncthreads();

    // ---- L4: [h2|x|dir](cols 0..543) @ W4 -> h3 (regs) -> rgb head ----
    {
        float C[16][4] = {};
        run_layer<34, 16, 16>(slab, 0, mr, gr, gc, Wpk + 46592, nh, lane, C);

        float pl[3] = {0.f, 0.f, 0.f}, ph[3] = {0.f, 0.f, 0.f};
        #pragma unroll
        for (int nt = 0; nt < 16; nt++) {
            int n = nh * 128 + nt * 8 + 2 * gc;
            float2 b = *(const float2*)&vb1[n];
            float h0 = fmaxf(C[nt][0] + b.x, 0.f);
            float h1 = fmaxf(C[nt][1] + b.y, 0.f);
            float h2 = fmaxf(C[nt][2] + b.x, 0.f);
            float h3 = fmaxf(C[nt][3] + b.y, 0.f);
            #pragma unroll
            for (int j = 0; j < 3; j++) {
                pl[j] += h0 * rwsm[n * 3 + j] + h1 * rwsm[(n + 1) * 3 + j];
                ph[j] += h2 * rwsm[n * 3 + j] + h3 * rwsm[(n + 1) * 3 + j];
            }
        }
        #pragma unroll
        for (int j = 0; j < 3; j++) {
            pl[j] += __shfl_xor_sync(0xffffffffu, pl[j], 1);
            pl[j] += __shfl_xor_sync(0xffffffffu, pl[j], 2);
            ph[j] += __shfl_xor_sync(0xffffffffu, ph[j], 1);
            ph[j] += __shfl_xor_sync(0xffffffffu, ph[j], 2);
        }
        if (gc == 0) {
            #pragma unroll
            for (int j = 0; j < 3; j++) {
                parth[(mr + gr) * 6 + nh * 3 + j]     = pl[j];
                parth[(mr + gr + 8) * 6 + nh * 3 + j] = ph[j];
            }
        }
    }
    __syncthreads();

    if (t < ROWS_CTA) {
        #pragma unroll
        for (int j = 0; j < 3; j++) {
            float s = parth[t * 6 + j] + parth[t * 6 + 3 + j] + __ldg(&rbias[j]);
            float sig = 1.0f / (1.0f + expf(-s));
            out[(rs0 + t) * 3 + j] = sig * 1.002f - 0.001f;
        }
    }
}

// ---------------- launch ----------------
extern "C" void kernel_launch(void* const* d_in, const int* in_sizes, int n_in,
                              void* d_out, int out_size)
{
    const float* means = (const float*)d_in[0];
    const float* stds  = (const float*)d_in[1];
    const float* vd    = (const float*)d_in[2];
    const float* table = (const float*)d_in[3];
    const float* dw1   = (const float*)d_in[4];
    const float* db1   = (const float*)d_in[5];
    const float* dw2   = (const float*)d_in[6];
    const float* db2   = (const float*)d_in[7];
    const float* vw0   = (const float*)d_in[8];
    const float* vb0   = (const float*)d_in[9];
    const float* vw1   = (const float*)d_in[10];
    const float* vb1   = (const float*)d_in[11];
    const float* rw    = (const float*)d_in[12];
    const float* rb    = (const float*)d_in[13];
    float* out = (float*)d_out;

    cudaFuncSetAttribute(mlp_mma_kernel, cudaFuncAttributeMaxDynamicSharedMemorySize, SM_TOTAL);

    prep_kernel<<<(PK_TOTAL_H2 + 255) / 256, 256>>>(dw1, dw2, vw0, vw1);

    dim3 g1(RS_TOTAL / 128, NUM_LEVELS);
    grid_encode_kernel<<<g1, 128>>>(means, stds, (const float4*)table);

    mlp_mma_kernel<<<NCTA, 256, SM_TOTAL>>>(vd, db1, db2, vb0, vb1, rw, rb, out);
}

// round 8
// speedup vs baseline: 1.5047x; 1.0079x over previous
#include <cuda_runtime.h>
#include <cuda_fp16.h>
#include <math.h>
#include <stdint.h>

// ---------------- problem constants ----------------
#define R_RAYS      4096
#define S_SAMPLES   32
#define RS_TOTAL    131072
#define M_SAMPLES   6
#define NUM_LEVELS  10
#define FEAT_DIM    40
#define HASHMASK    2097151u
#define RGB_ELEMS   393216

#define ROWS_CTA    64
#define NCTA        (RS_TOTAL / ROWS_CTA)     // 2048

__constant__ int c_offsets[NUM_LEVELS] = {
    0, 4920, 40864, 315496, 2412648, 4509800, 6606952, 8704104, 10801256, 12898408
};
__constant__ int c_sizes[NUM_LEVELS] = {
    4920, 35944, 274632, 2097152, 2097152, 2097152, 2097152, 2097152, 2097152, 2097152
};

// fp16 feature scratch: [rs][40]
__device__ __half g_feat_h[RS_TOTAL * FEAT_DIM];

// packed fp16 weight fragments. Layer bases (half2):
//   L1 = 0      (1536)   k-pad 40->48->KT3, N=64
//   L2 = 1536   (8192)   KT4,  N=256
//   L3 = 9728   (32768)  KT16, N=256  (x only; dir folded into bias)
//   L4 = 42496  (65536)  KT32, N=256  (h2|x only)
#define PK_TOTAL_H2 108032
__device__ __align__(16) __half2 Wpk[PK_TOTAL_H2];

#define SLAB 568   // slab row stride in halves

// ---------------- mma helper ----------------
__device__ __forceinline__ void mma16816(float c[4],
    unsigned a0, unsigned a1, unsigned a2, unsigned a3,
    unsigned b0, unsigned b1)
{
    asm volatile(
        "mma.sync.aligned.m16n8k16.row.col.f32.f16.f16.f32 "
        "{%0,%1,%2,%3}, {%4,%5,%6,%7}, {%8,%9}, {%0,%1,%2,%3};"
        : "+f"(c[0]), "+f"(c[1]), "+f"(c[2]), "+f"(c[3])
        : "r"(a0), "r"(a1), "r"(a2), "r"(a3), "r"(b0), "r"(b1));
}

// named barrier over one (m-tile, both n-halves) pair: 2 warps = 64 threads
__device__ __forceinline__ void bar_pair(int id) {
    asm volatile("bar.sync %0, 64;" :: "r"(id) : "memory");
}

// ---------------- kernel 0: weight prep ----------------
__global__ __launch_bounds__(256) void prep_kernel(
    const float* __restrict__ dw1, const float* __restrict__ dw2,
    const float* __restrict__ vw0, const float* __restrict__ vw1)
{
    int idx = blockIdx.x * 256 + threadIdx.x;
    if (idx >= PK_TOTAL_H2) return;

    int local, NP, layer;
    if (idx < 1536)        { layer = 1; local = idx;         NP = 4;  }
    else if (idx < 9728)   { layer = 2; local = idx - 1536;  NP = 16; }
    else if (idx < 42496)  { layer = 3; local = idx - 9728;  NP = 16; }
    else                   { layer = 4; local = idx - 42496; NP = 16; }

    const int j    = local & 3;
    const int lane = (local >> 2) & 31;
    const int rem  = local >> 7;
    const int np   = rem % NP;
    const int kt   = rem / NP;

    const int nt  = np * 2 + (j >> 1);
    const int reg = j & 1;
    const int n   = nt * 8 + (lane >> 2);
    const int k   = kt * 16 + reg * 8 + (lane & 3) * 2;

    float v0 = 0.f, v1 = 0.f;
    if (layer == 1) {
        if (k     < 40) v0 = dw1[k * 64 + n];
        if (k + 1 < 40) v1 = dw1[(k + 1) * 64 + n];
    } else if (layer == 2) {
        v0 = dw2[k * 256 + n];
        v1 = dw2[(k + 1) * 256 + n];
    } else if (layer == 3) {
        v0 = vw0[k * 256 + n];            // k < 256 by construction
        v1 = vw0[(k + 1) * 256 + n];
    } else {
        v0 = vw1[k * 256 + n];            // k < 512 by construction
        v1 = vw1[(k + 1) * 256 + n];
    }
    Wpk[idx] = __floats2half2_rn(v0, v1);
}

// ---------------- kernel 1: hash-grid encode (validated R7) ----------------
__global__ __launch_bounds__(128) void grid_encode_kernel(
    const float* __restrict__ means,
    const float* __restrict__ stds,
    const float4* __restrict__ table)
{
    int rs = blockIdx.x * blockDim.x + threadIdx.x;
    int level = blockIdx.y;

    const float scale = (float)(16 << level);
    const unsigned res = (unsigned)((16 << level) + 1);
    const bool dense = (level < 3);
    const int off = c_offsets[level];
    const unsigned size_m1 = (unsigned)(c_sizes[level] - 1);

    float acc0 = 0.f, acc1 = 0.f, acc2 = 0.f, acc3 = 0.f;

    #pragma unroll
    for (int m = 0; m < M_SAMPLES; m++) {
        const int pidx = rs * M_SAMPLES + m;
        const float mx = means[pidx * 3 + 0];
        const float my = means[pidx * 3 + 1];
        const float mz = means[pidx * 3 + 2];
        const float sd = stds[pidx];
        const float wl = erff(1.0f / (2.8284271247461903f * sd * scale));

        float px = (mx + 1.0f) * 0.5f * scale + 0.5f;
        float py = (my + 1.0f) * 0.5f * scale + 0.5f;
        float pz = (mz + 1.0f) * 0.5f * scale + 0.5f;
        float f0x = floorf(px), f0y = floorf(py), f0z = floorf(pz);
        float fx = px - f0x, fy = py - f0y, fz = pz - f0z;
        unsigned ux = (unsigned)f0x, uy = (unsigned)f0y, uz = (unsigned)f0z;

        #pragma unroll
        for (int c = 0; c < 8; c++) {
            const unsigned bx = c & 1u, by = (c >> 1) & 1u, bz = (c >> 2) & 1u;
            const unsigned cx = ux + bx, cy = uy + by, cz = uz + bz;
            unsigned idx;
            if (dense) { idx = (cx * res + cy) * res + cz; idx = min(idx, size_m1); }
            else { idx = (cx * 1u) ^ (cy * 2654435761u) ^ (cz * 805459861u); idx &= HASHMASK; }
            const float wx = bx ? fx : (1.0f - fx);
            const float wy = by ? fy : (1.0f - fy);
            const float wz = bz ? fz : (1.0f - fz);
            const float w = wx * wy * wz * wl;
            const float4 tt = __ldg(table + off + (int)idx);
            acc0 += w * tt.x; acc1 += w * tt.y; acc2 += w * tt.z; acc3 += w * tt.w;
        }
    }
    const float inv = 1.0f / 6.0f;
    __half2 lo = __floats2half2_rn(acc0 * inv, acc1 * inv);
    __half2 hi = __floats2half2_rn(acc2 * inv, acc3 * inv);
    *(__half2*)&g_feat_h[rs * FEAT_DIM + level * 4]     = lo;
    *(__half2*)&g_feat_h[rs * FEAT_DIM + level * 4 + 2] = hi;
}

// ---------------- generic fragment-GEMM layer over the smem slab ----------------
template<int KT, int NTW, int NP>
__device__ __forceinline__ void run_layer(
    const __half* slab, int acol0, int mr, int gr, int gc,
    const __half2* __restrict__ wpk, int nh, int lane, float C[][4])
{
    const __half* arow = slab + (mr + gr) * SLAB + acol0 + gc * 2;
    const uint4* wbase = (const uint4*)wpk + (size_t)(nh * (NP / 2)) * 32 + lane;
    #pragma unroll 1
    for (int kt = 0; kt < KT; kt++) {
        const __half* ap = arow + kt * 16;
        unsigned a0 = *(const unsigned*)(ap);
        unsigned a2 = *(const unsigned*)(ap + 8);
        unsigned a1 = *(const unsigned*)(ap + 8 * SLAB);
        unsigned a3 = *(const unsigned*)(ap + 8 * SLAB + 8);
        const uint4* wp = wbase + (size_t)kt * NP * 32;
        #pragma unroll
        for (int p = 0; p < NTW / 2; p++) {
            uint4 b = __ldg(wp + p * 32);
            mma16816(C[2 * p],     a0, a1, a2, a3, b.x, b.y);
            mma16816(C[2 * p + 1], a0, a1, a2, a3, b.z, b.w);
        }
    }
}

// ---------------- kernel 2: MLP, 64 rows/CTA, occ 2, per-pair barriers ----------------
// smem: slab 64x568 halves (72704B) | dirsm 64f | d3s 512f | d4s 512f | rwsm 768f | parth 384f
#define SM_DIR   72704
#define SM_D3    72960
#define SM_D4    75008
#define SM_RW    77056
#define SM_PARTH 80128
#define SM_TOTAL 81664

__global__ __launch_bounds__(256, 2) void mlp_mma_kernel(
    const float* __restrict__ vd,
    const float* __restrict__ db1, const float* __restrict__ db2,
    const float* __restrict__ vb0, const float* __restrict__ vb1,
    const float* __restrict__ vw0, const float* __restrict__ vw1,
    const float* __restrict__ rw,  const float* __restrict__ rbias,
    float* __restrict__ out)
{
    extern __shared__ char dyn[];
    __half* slab = (__half*)dyn;
    float* dirsm = (float*)(dyn + SM_DIR);
    float* d3s   = (float*)(dyn + SM_D3);
    float* d4s   = (float*)(dyn + SM_D4);
    float* rwsm  = (float*)(dyn + SM_RW);
    float* parth = (float*)(dyn + SM_PARTH);

    const int t = threadIdx.x;
    const int w = t >> 5, lane = t & 31;
    const int gr = lane >> 2, gc = lane & 3;
    const int mt = w & 3, nh = w >> 2;      // 4 m-tiles x 2 n-halves
    const int mr = mt * 16;
    const int bid = 1 + mt;                 // named barrier id for this pair
    const int ray = mt >> 1;                // m-tiles 0,1 -> ray 0; 2,3 -> ray 1
    const int rs0 = blockIdx.x * ROWS_CTA;

    // rw -> smem
    for (int i = t; i < 768; i += 256) rwsm[i] = rw[i];

    // dir encoding: 2 rays x 32 cols (cols >= 27 zero)
    if (t < 64) {
        int rayi = t >> 5, c = t & 31;
        int rg = blockIdx.x * 2 + rayi;
        float v = 0.f;
        if (c < 3) v = vd[rg * 3 + c];
        else if (c < 15) { int j = c - 3;  v = sinf(vd[rg * 3 + (j % 3)] * (float)(1 << (j / 3))); }
        else if (c < 27) { int j = c - 15; v = cosf(vd[rg * 3 + (j % 3)] * (float)(1 << (j / 3))); }
        dirsm[t] = v;
        // zero feat pad cols 40..47
        *(uint4*)&slab[t * SLAB + 40] = make_uint4(0, 0, 0, 0);
    }

    // feat (fp16) -> slab cols 0..39
    #pragma unroll
    for (int i = t; i < ROWS_CTA * 20; i += 256) {
        int r = i / 20, c = i % 20;
        *(unsigned*)&slab[r * SLAB + c * 2] =
            *(const unsigned*)&g_feat_h[(rs0 + r) * FEAT_DIM + c * 2];
    }
    __syncthreads();

    // dir contribution folded to per-(ray,channel) scalars (fp32)
    {
        const int ry = t >> 7;
        const int ch = (t & 127) * 2;
        const float* dv = &dirsm[ry * 32];
        float a3 = 0.f, b3 = 0.f, a4 = 0.f, b4 = 0.f;
        #pragma unroll
        for (int j = 0; j < 27; j++) {
            const float d = dv[j];
            const float2 w3 = *(const float2*)&vw0[(256 + j) * 256 + ch];
            const float2 w4 = *(const float2*)&vw1[(512 + j) * 256 + ch];
            a3 += d * w3.x; b3 += d * w3.y;
            a4 += d * w4.x; b4 += d * w4.y;
        }
        *(float2*)&d3s[ry * 256 + ch] = make_float2(a3, b3);
        *(float2*)&d4s[ry * 256 + ch] = make_float2(a4, b4);
    }
    __syncthreads();

    // ---- L1: feat(cols 0..47) @ W1 -> h1 (relu) -> cols 64..127 ----
    {
        float C[4][4] = {};
        run_layer<3, 4, 4>(slab, 0, mr, gr, gc, Wpk, nh, lane, C);
        #pragma unroll
        for (int nt = 0; nt < 4; nt++) {
            int n = nh * 32 + nt * 8 + 2 * gc;
            float2 b = *(const float2*)&db1[n];
            __half2 lo = __floats2half2_rn(fmaxf(C[nt][0] + b.x, 0.f), fmaxf(C[nt][1] + b.y, 0.f));
            __half2 hi = __floats2half2_rn(fmaxf(C[nt][2] + b.x, 0.f), fmaxf(C[nt][3] + b.y, 0.f));
            *(__half2*)&slab[(mr + gr) * SLAB + 64 + n]     = lo;
            *(__half2*)&slab[(mr + gr + 8) * SLAB + 64 + n] = hi;
        }
    }
    bar_pair(bid);

    // ---- L2: h1(cols 64..127) @ W2 -> x (cols 256..511); density ----
    {
        float C[16][4] = {};
        run_layer<4, 16, 16>(slab, 64, mr, gr, gc, Wpk + 1536, nh, lane, C);
        if (nh == 0 && gc == 0) {
            float xa = C[0][0] + __ldg(&db2[0]) - 1.0f;
            float xb = C[0][2] + __ldg(&db2[0]) - 1.0f;
            out[RGB_ELEMS + rs0 + mr + gr]     = fmaxf(xa, 0.f) + log1pf(expf(-fabsf(xa)));
            out[RGB_ELEMS + rs0 + mr + gr + 8] = fmaxf(xb, 0.f) + log1pf(expf(-fabsf(xb)));
        }
        #pragma unroll
        for (int nt = 0; nt < 16; nt++) {
            int n = nh * 128 + nt * 8 + 2 * gc;
            float2 b = *(const float2*)&db2[n];
            __half2 lo = __floats2half2_rn(C[nt][0] + b.x, C[nt][1] + b.y);
            __half2 hi = __floats2half2_rn(C[nt][2] + b.x, C[nt][3] + b.y);
            *(__half2*)&slab[(mr + gr) * SLAB + 256 + n]     = lo;
            *(__half2*)&slab[(mr + gr + 8) * SLAB + 256 + n] = hi;
        }
    }
    bar_pair(bid);

    // ---- L3: x(cols 256..511) @ W3 + dirfold -> h2 (relu) -> cols 0..255 ----
    {
        float C[16][4] = {};
        run_layer<16, 16, 16>(slab, 256, mr, gr, gc, Wpk + 9728, nh, lane, C);
        #pragma unroll
        for (int nt = 0; nt < 16; nt++) {
            int n = nh * 128 + nt * 8 + 2 * gc;
            float2 b = *(const float2*)&vb0[n];
            float2 d = *(const float2*)&d3s[ray * 256 + n];
            float b0 = b.x + d.x, b1 = b.y + d.y;
            __half2 lo = __floats2half2_rn(fmaxf(C[nt][0] + b0, 0.f), fmaxf(C[nt][1] + b1, 0.f));
            __half2 hi = __floats2half2_rn(fmaxf(C[nt][2] + b0, 0.f), fmaxf(C[nt][3] + b1, 0.f));
            *(__half2*)&slab[(mr + gr) * SLAB + n]     = lo;
            *(__half2*)&slab[(mr + gr + 8) * SLAB + n] = hi;
        }
    }
    bar_pair(bid);

    // ---- L4: [h2|x](cols 0..511) @ W4 + dirfold -> h3 (regs) -> rgb head ----
    {
        float C[16][4] = {};
        run_layer<32, 16, 16>(slab, 0, mr, gr, gc, Wpk + 42496, nh, lane, C);

        float pl[3] = {0.f, 0.f, 0.f}, ph[3] = {0.f, 0.f, 0.f};
        #pragma unroll
        for (int nt = 0; nt < 16; nt++) {
            int n = nh * 128 + nt * 8 + 2 * gc;
            float2 b = *(const float2*)&vb1[n];
            float2 d = *(const float2*)&d4s[ray * 256 + n];
            float b0 = b.x + d.x, b1 = b.y + d.y;
            float h0 = fmaxf(C[nt][0] + b0, 0.f);
            float h1 = fmaxf(C[nt][1] + b1, 0.f);
            float h2 = fmaxf(C[nt][2] + b0, 0.f);
            float h3 = fmaxf(C[nt][3] + b1, 0.f);
            #pragma unroll
            for (int j = 0; j < 3; j++) {
                pl[j] += h0 * rwsm[n * 3 + j] + h1 * rwsm[(n + 1) * 3 + j];
                ph[j] += h2 * rwsm[n * 3 + j] + h3 * rwsm[(n + 1) * 3 + j];
            }
        }
        #pragma unroll
        for (int j = 0; j < 3; j++) {
            pl[j] += __shfl_xor_sync(0xffffffffu, pl[j], 1);
            pl[j] += __shfl_xor_sync(0xffffffffu, pl[j], 2);
            ph[j] += __shfl_xor_sync(0xffffffffu, ph[j], 1);
            ph[j] += __shfl_xor_sync(0xffffffffu, ph[j], 2);
        }
        if (gc == 0) {
            #pragma unroll
            for (int j = 0; j < 3; j++) {
                parth[(mr + gr) * 6 + nh * 3 + j]     = pl[j];
                parth[(mr + gr + 8) * 6 + nh * 3 + j] = ph[j];
            }
        }
    }
    __syncthreads();

    if (t < ROWS_CTA) {
        #pragma unroll
        for (int j = 0; j < 3; j++) {
            float s = parth[t * 6 + j] + parth[t * 6 + 3 + j] + __ldg(&rbias[j]);
            float sig = 1.0f / (1.0f + expf(-s));
            out[(rs0 + t) * 3 + j] = sig * 1.002f - 0.001f;
        }
    }
}

// ---------------- launch ----------------
extern "C" void kernel_launch(void* const* d_in, const int* in_sizes, int n_in,
                              void* d_out, int out_size)
{
    const float* means = (const float*)d_in[0];
    const float* stds  = (const float*)d_in[1];
    const float* vd    = (const float*)d_in[2];
    const float* table = (const float*)d_in[3];
    const float* dw1   = (const float*)d_in[4];
    const float* db1   = (const float*)d_in[5];
    const float* dw2   = (const float*)d_in[6];
    const float* db2   = (const float*)d_in[7];
    const float* vw0   = (const float*)d_in[8];
    const float* vb0   = (const float*)d_in[9];
    const float* vw1   = (const float*)d_in[10];
    const float* vb1   = (const float*)d_in[11];
    const float* rw    = (const float*)d_in[12];
    const float* rb    = (const float*)d_in[13];
    float* out = (float*)d_out;

    cudaFuncSetAttribute(mlp_mma_kernel, cudaFuncAttributeMaxDynamicSharedMemorySize, SM_TOTAL);

    prep_kernel<<<(PK_TOTAL_H2 + 255) / 256, 256>>>(dw1, dw2, vw0, vw1);

    dim3 g1(RS_TOTAL / 128, NUM_LEVELS);
    grid_encode_kernel<<<g1, 128>>>(means, stds, (const float4*)table);

    mlp_mma_kernel<<<NCTA, 256, SM_TOTAL>>>(vd, db1, db2, vb0, vb1,
                                            vw0, vw1, rw, rb, out);
}

// round 9
// speedup vs baseline: 1.5977x; 1.0618x over previous
#include <cuda_runtime.h>
#include <cuda_fp16.h>
#include <math.h>
#include <stdint.h>

// ---------------- problem constants ----------------
#define R_RAYS      4096
#define S_SAMPLES   32
#define RS_TOTAL    131072
#define M_SAMPLES   6
#define NUM_LEVELS  10
#define FEAT_DIM    40
#define HASHMASK    2097151u
#define RGB_ELEMS   393216

#define ROWS_CTA    64
#define NCTA        (RS_TOTAL / ROWS_CTA)     // 2048

__constant__ int c_offsets[NUM_LEVELS] = {
    0, 4920, 40864, 315496, 2412648, 4509800, 6606952, 8704104, 10801256, 12898408
};
__constant__ int c_sizes[NUM_LEVELS] = {
    4920, 35944, 274632, 2097152, 2097152, 2097152, 2097152, 2097152, 2097152, 2097152
};

// fp16 feature scratch: [rs][40]
__device__ __half g_feat_h[RS_TOTAL * FEAT_DIM];

// packed fp16 weight fragments. Layer bases (half2):
//   L1 = 0      (1536)   KT3,  N=64
//   L2 = 1536   (8192)   KT4,  N=256
//   L3 = 9728   (32768)  KT16, N=256  (x only; dir folded into bias)
//   L4 = 42496  (65536)  KT32, N=256  (h2|x only)
#define PK_TOTAL_H2 108032
__device__ __align__(16) __half2 Wpk[PK_TOTAL_H2];

#define SLAB 568   // slab row stride in halves

// ---------------- mma helper ----------------
__device__ __forceinline__ void mma16816(float c[4],
    unsigned a0, unsigned a1, unsigned a2, unsigned a3,
    unsigned b0, unsigned b1)
{
    asm volatile(
        "mma.sync.aligned.m16n8k16.row.col.f32.f16.f16.f32 "
        "{%0,%1,%2,%3}, {%4,%5,%6,%7}, {%8,%9}, {%0,%1,%2,%3};"
        : "+f"(c[0]), "+f"(c[1]), "+f"(c[2]), "+f"(c[3])
        : "r"(a0), "r"(a1), "r"(a2), "r"(a3), "r"(b0), "r"(b1));
}

// named barrier over one m-pair row-group: 4 warps = 128 threads
__device__ __forceinline__ void bar_grp(int id) {
    asm volatile("bar.sync %0, 128;" :: "r"(id) : "memory");
}

// ---------------- kernel 0: weight prep ----------------
__global__ __launch_bounds__(256) void prep_kernel(
    const float* __restrict__ dw1, const float* __restrict__ dw2,
    const float* __restrict__ vw0, const float* __restrict__ vw1)
{
    int idx = blockIdx.x * 256 + threadIdx.x;
    if (idx >= PK_TOTAL_H2) return;

    int local, NP, layer;
    if (idx < 1536)        { layer = 1; local = idx;         NP = 4;  }
    else if (idx < 9728)   { layer = 2; local = idx - 1536;  NP = 16; }
    else if (idx < 42496)  { layer = 3; local = idx - 9728;  NP = 16; }
    else                   { layer = 4; local = idx - 42496; NP = 16; }

    const int j    = local & 3;
    const int lane = (local >> 2) & 31;
    const int rem  = local >> 7;
    const int np   = rem % NP;
    const int kt   = rem / NP;

    const int nt  = np * 2 + (j >> 1);
    const int reg = j & 1;
    const int n   = nt * 8 + (lane >> 2);
    const int k   = kt * 16 + reg * 8 + (lane & 3) * 2;

    float v0 = 0.f, v1 = 0.f;
    if (layer == 1) {
        if (k     < 40) v0 = dw1[k * 64 + n];
        if (k + 1 < 40) v1 = dw1[(k + 1) * 64 + n];
    } else if (layer == 2) {
        v0 = dw2[k * 256 + n];
        v1 = dw2[(k + 1) * 256 + n];
    } else if (layer == 3) {
        v0 = vw0[k * 256 + n];
        v1 = vw0[(k + 1) * 256 + n];
    } else {
        v0 = vw1[k * 256 + n];
        v1 = vw1[(k + 1) * 256 + n];
    }
    Wpk[idx] = __floats2half2_rn(v0, v1);
}

// ---------------- kernel 1: hash-grid encode (validated R7) ----------------
__global__ __launch_bounds__(128) void grid_encode_kernel(
    const float* __restrict__ means,
    const float* __restrict__ stds,
    const float4* __restrict__ table)
{
    int rs = blockIdx.x * blockDim.x + threadIdx.x;
    int level = blockIdx.y;

    const float scale = (float)(16 << level);
    const unsigned res = (unsigned)((16 << level) + 1);
    const bool dense = (level < 3);
    const int off = c_offsets[level];
    const unsigned size_m1 = (unsigned)(c_sizes[level] - 1);

    float acc0 = 0.f, acc1 = 0.f, acc2 = 0.f, acc3 = 0.f;

    #pragma unroll
    for (int m = 0; m < M_SAMPLES; m++) {
        const int pidx = rs * M_SAMPLES + m;
        const float mx = means[pidx * 3 + 0];
        const float my = means[pidx * 3 + 1];
        const float mz = means[pidx * 3 + 2];
        const float sd = stds[pidx];
        const float wl = erff(1.0f / (2.8284271247461903f * sd * scale));

        float px = (mx + 1.0f) * 0.5f * scale + 0.5f;
        float py = (my + 1.0f) * 0.5f * scale + 0.5f;
        float pz = (mz + 1.0f) * 0.5f * scale + 0.5f;
        float f0x = floorf(px), f0y = floorf(py), f0z = floorf(pz);
        float fx = px - f0x, fy = py - f0y, fz = pz - f0z;
        unsigned ux = (unsigned)f0x, uy = (unsigned)f0y, uz = (unsigned)f0z;

        #pragma unroll
        for (int c = 0; c < 8; c++) {
            const unsigned bx = c & 1u, by = (c >> 1) & 1u, bz = (c >> 2) & 1u;
            const unsigned cx = ux + bx, cy = uy + by, cz = uz + bz;
            unsigned idx;
            if (dense) { idx = (cx * res + cy) * res + cz; idx = min(idx, size_m1); }
            else { idx = (cx * 1u) ^ (cy * 2654435761u) ^ (cz * 805459861u); idx &= HASHMASK; }
            const float wx = bx ? fx : (1.0f - fx);
            const float wy = by ? fy : (1.0f - fy);
            const float wz = bz ? fz : (1.0f - fz);
            const float w = wx * wy * wz * wl;
            const float4 tt = __ldg(table + off + (int)idx);
            acc0 += w * tt.x; acc1 += w * tt.y; acc2 += w * tt.z; acc3 += w * tt.w;
        }
    }
    const float inv = 1.0f / 6.0f;
    __half2 lo = __floats2half2_rn(acc0 * inv, acc1 * inv);
    __half2 hi = __floats2half2_rn(acc2 * inv, acc3 * inv);
    *(__half2*)&g_feat_h[rs * FEAT_DIM + level * 4]     = lo;
    *(__half2*)&g_feat_h[rs * FEAT_DIM + level * 4 + 2] = hi;
}

// ---------------- fragment-GEMM: warp = 2 m-tiles x NTW n-tiles ----------------
// A: slab rows [mp*32 .. mp*32+31], cols [acol0 .. acol0+KT*16)
// B: this warp uses np in [nq*NTW/2, (nq+1)*NTW/2); each B uint4 feeds 4 mma.
template<int KT, int NTW, int NP>
__device__ __forceinline__ void run_layer2(
    const __half* slab, int acol0, int mp, int gr, int gc,
    const __half2* __restrict__ wpk, int nq, int lane, float C[2][NTW][4])
{
    const __half* arow0 = slab + (mp * 32 + gr) * SLAB + acol0 + gc * 2;
    const uint4* wbase = (const uint4*)wpk + (size_t)(nq * (NTW / 2)) * 32 + lane;
    #pragma unroll 1
    for (int kt = 0; kt < KT; kt++) {
        const __half* ap0 = arow0 + kt * 16;
        const __half* ap1 = ap0 + 16 * SLAB;
        unsigned a0 = *(const unsigned*)(ap0);
        unsigned a2 = *(const unsigned*)(ap0 + 8);
        unsigned a1 = *(const unsigned*)(ap0 + 8 * SLAB);
        unsigned a3 = *(const unsigned*)(ap0 + 8 * SLAB + 8);
        unsigned a4 = *(const unsigned*)(ap1);
        unsigned a6 = *(const unsigned*)(ap1 + 8);
        unsigned a5 = *(const unsigned*)(ap1 + 8 * SLAB);
        unsigned a7 = *(const unsigned*)(ap1 + 8 * SLAB + 8);
        const uint4* wp = wbase + (size_t)kt * NP * 32;
        #pragma unroll
        for (int p = 0; p < NTW / 2; p++) {
            uint4 b = __ldg(wp + p * 32);
            mma16816(C[0][2 * p],     a0, a1, a2, a3, b.x, b.y);
            mma16816(C[0][2 * p + 1], a0, a1, a2, a3, b.z, b.w);
            mma16816(C[1][2 * p],     a4, a5, a6, a7, b.x, b.y);
            mma16816(C[1][2 * p + 1], a4, a5, a6, a7, b.z, b.w);
        }
    }
}

// ---------------- kernel 2: MLP, 64 rows/CTA, occ 2, 2x M-blocked warps ----------------
// smem: slab 64x568 halves (72704B) | dirsm 64f | d3s 512f | d4s 512f | rwsm 768f | parth 768f
#define SM_DIR   72704
#define SM_D3    72960
#define SM_D4    75008
#define SM_RW    77056
#define SM_PARTH 80128
#define SM_TOTAL 83200

__global__ __launch_bounds__(256, 2) void mlp_mma_kernel(
    const float* __restrict__ vd,
    const float* __restrict__ db1, const float* __restrict__ db2,
    const float* __restrict__ vb0, const float* __restrict__ vb1,
    const float* __restrict__ vw0, const float* __restrict__ vw1,
    const float* __restrict__ rw,  const float* __restrict__ rbias,
    float* __restrict__ out)
{
    extern __shared__ char dyn[];
    __half* slab = (__half*)dyn;
    float* dirsm = (float*)(dyn + SM_DIR);
    float* d3s   = (float*)(dyn + SM_D3);
    float* d4s   = (float*)(dyn + SM_D4);
    float* rwsm  = (float*)(dyn + SM_RW);
    float* parth = (float*)(dyn + SM_PARTH);

    const int t = threadIdx.x;
    const int w = t >> 5, lane = t & 31;
    const int gr = lane >> 2, gc = lane & 3;
    const int mp = w & 1;                   // m-pair: rows mp*32 .. mp*32+31
    const int nq = w >> 1;                  // n-quarter: 64 channels at nq*64
    const int bid = 1 + mp;                 // named barrier per row-group
    const int rs0 = blockIdx.x * ROWS_CTA;

    // rw -> smem
    for (int i = t; i < 768; i += 256) rwsm[i] = rw[i];

    // dir encoding: 2 rays x 32 cols (cols >= 27 zero)
    if (t < 64) {
        int rayi = t >> 5, c = t & 31;
        int rg = blockIdx.x * 2 + rayi;
        float v = 0.f;
        if (c < 3) v = vd[rg * 3 + c];
        else if (c < 15) { int j = c - 3;  v = sinf(vd[rg * 3 + (j % 3)] * (float)(1 << (j / 3))); }
        else if (c < 27) { int j = c - 15; v = cosf(vd[rg * 3 + (j % 3)] * (float)(1 << (j / 3))); }
        dirsm[t] = v;
        // zero feat pad cols 40..47
        *(uint4*)&slab[t * SLAB + 40] = make_uint4(0, 0, 0, 0);
    }

    // feat (fp16) -> slab cols 0..39
    #pragma unroll
    for (int i = t; i < ROWS_CTA * 20; i += 256) {
        int r = i / 20, c = i % 20;
        *(unsigned*)&slab[r * SLAB + c * 2] =
            *(const unsigned*)&g_feat_h[(rs0 + r) * FEAT_DIM + c * 2];
    }
    __syncthreads();

    // dir contribution folded to per-(ray,channel) scalars (fp32)
    {
        const int ry = t >> 7;
        const int ch = (t & 127) * 2;
        const float* dv = &dirsm[ry * 32];
        float a3 = 0.f, b3 = 0.f, a4 = 0.f, b4 = 0.f;
        #pragma unroll
        for (int j = 0; j < 27; j++) {
            const float d = dv[j];
            const float2 w3 = *(const float2*)&vw0[(256 + j) * 256 + ch];
            const float2 w4 = *(const float2*)&vw1[(512 + j) * 256 + ch];
            a3 += d * w3.x; b3 += d * w3.y;
            a4 += d * w4.x; b4 += d * w4.y;
        }
        *(float2*)&d3s[ry * 256 + ch] = make_float2(a3, b3);
        *(float2*)&d4s[ry * 256 + ch] = make_float2(a4, b4);
    }
    __syncthreads();

    // ---- L1: feat(cols 0..47) @ W1 -> h1 (relu) -> cols 64..127 ----
    {
        float C[2][2][4] = {};
        run_layer2<3, 2, 4>(slab, 0, mp, gr, gc, Wpk, nq, lane, C);
        #pragma unroll
        for (int mm = 0; mm < 2; mm++) {
            const int r0 = mp * 32 + mm * 16 + gr;
            #pragma unroll
            for (int nt = 0; nt < 2; nt++) {
                int n = nq * 16 + nt * 8 + 2 * gc;
                float2 b = *(const float2*)&db1[n];
                __half2 lo = __floats2half2_rn(fmaxf(C[mm][nt][0] + b.x, 0.f), fmaxf(C[mm][nt][1] + b.y, 0.f));
                __half2 hi = __floats2half2_rn(fmaxf(C[mm][nt][2] + b.x, 0.f), fmaxf(C[mm][nt][3] + b.y, 0.f));
                *(__half2*)&slab[r0 * SLAB + 64 + n]       = lo;
                *(__half2*)&slab[(r0 + 8) * SLAB + 64 + n] = hi;
            }
        }
    }
    bar_grp(bid);

    // ---- L2: h1(cols 64..127) @ W2 -> x (cols 256..511); density ----
    {
        float C[2][8][4] = {};
        run_layer2<4, 8, 16>(slab, 64, mp, gr, gc, Wpk + 1536, nq, lane, C);
        #pragma unroll
        for (int mm = 0; mm < 2; mm++) {
            const int r0 = mp * 32 + mm * 16 + gr;
            if (nq == 0 && gc == 0) {
                float xa = C[mm][0][0] + __ldg(&db2[0]) - 1.0f;
                float xb = C[mm][0][2] + __ldg(&db2[0]) - 1.0f;
                out[RGB_ELEMS + rs0 + r0]     = fmaxf(xa, 0.f) + log1pf(expf(-fabsf(xa)));
                out[RGB_ELEMS + rs0 + r0 + 8] = fmaxf(xb, 0.f) + log1pf(expf(-fabsf(xb)));
            }
            #pragma unroll
            for (int nt = 0; nt < 8; nt++) {
                int n = nq * 64 + nt * 8 + 2 * gc;
                float2 b = *(const float2*)&db2[n];
                __half2 lo = __floats2half2_rn(C[mm][nt][0] + b.x, C[mm][nt][1] + b.y);
                __half2 hi = __floats2half2_rn(C[mm][nt][2] + b.x, C[mm][nt][3] + b.y);
                *(__half2*)&slab[r0 * SLAB + 256 + n]       = lo;
                *(__half2*)&slab[(r0 + 8) * SLAB + 256 + n] = hi;
            }
        }
    }
    bar_grp(bid);

    // ---- L3: x(cols 256..511) @ W3 + dirfold -> h2 (relu) -> cols 0..255 ----
    {
        float C[2][8][4] = {};
        run_layer2<16, 8, 16>(slab, 256, mp, gr, gc, Wpk + 9728, nq, lane, C);
        #pragma unroll
        for (int mm = 0; mm < 2; mm++) {
            const int r0 = mp * 32 + mm * 16 + gr;
            #pragma unroll
            for (int nt = 0; nt < 8; nt++) {
                int n = nq * 64 + nt * 8 + 2 * gc;
                float2 b = *(const float2*)&vb0[n];
                float2 d = *(const float2*)&d3s[mp * 256 + n];
                float b0 = b.x + d.x, b1 = b.y + d.y;
                __half2 lo = __floats2half2_rn(fmaxf(C[mm][nt][0] + b0, 0.f), fmaxf(C[mm][nt][1] + b1, 0.f));
                __half2 hi = __floats2half2_rn(fmaxf(C[mm][nt][2] + b0, 0.f), fmaxf(C[mm][nt][3] + b1, 0.f));
                *(__half2*)&slab[r0 * SLAB + n]       = lo;
                *(__half2*)&slab[(r0 + 8) * SLAB + n] = hi;
            }
        }
    }
    bar_grp(bid);

    // ---- L4: [h2|x](cols 0..511) @ W4 + dirfold -> h3 (regs) -> rgb head ----
    {
        float C[2][8][4] = {};
        run_layer2<32, 8, 16>(slab, 0, mp, gr, gc, Wpk + 42496, nq, lane, C);

        #pragma unroll
        for (int mm = 0; mm < 2; mm++) {
            const int r0 = mp * 32 + mm * 16 + gr;
            float pl[3] = {0.f, 0.f, 0.f}, ph[3] = {0.f, 0.f, 0.f};
            #pragma unroll
            for (int nt = 0; nt < 8; nt++) {
                int n = nq * 64 + nt * 8 + 2 * gc;
                float2 b = *(const float2*)&vb1[n];
                float2 d = *(const float2*)&d4s[mp * 256 + n];
                float b0 = b.x + d.x, b1 = b.y + d.y;
                float h0 = fmaxf(C[mm][nt][0] + b0, 0.f);
                float h1 = fmaxf(C[mm][nt][1] + b1, 0.f);
                float h2 = fmaxf(C[mm][nt][2] + b0, 0.f);
                float h3 = fmaxf(C[mm][nt][3] + b1, 0.f);
                #pragma unroll
                for (int j = 0; j < 3; j++) {
                    pl[j] += h0 * rwsm[n * 3 + j] + h1 * rwsm[(n + 1) * 3 + j];
                    ph[j] += h2 * rwsm[n * 3 + j] + h3 * rwsm[(n + 1) * 3 + j];
                }
            }
            #pragma unroll
            for (int j = 0; j < 3; j++) {
                pl[j] += __shfl_xor_sync(0xffffffffu, pl[j], 1);
                pl[j] += __shfl_xor_sync(0xffffffffu, pl[j], 2);
                ph[j] += __shfl_xor_sync(0xffffffffu, ph[j], 1);
                ph[j] += __shfl_xor_sync(0xffffffffu, ph[j], 2);
            }
            if (gc == 0) {
                #pragma unroll
                for (int j = 0; j < 3; j++) {
                    parth[r0 * 12 + nq * 3 + j]       = pl[j];
                    parth[(r0 + 8) * 12 + nq * 3 + j] = ph[j];
                }
            }
        }
    }
    __syncthreads();

    if (t < ROWS_CTA) {
        #pragma unroll
        for (int j = 0; j < 3; j++) {
            float s = parth[t * 12 + j] + parth[t * 12 + 3 + j]
                    + parth[t * 12 + 6 + j] + parth[t * 12 + 9 + j] + __ldg(&rbias[j]);
            float sig = 1.0f / (1.0f + expf(-s));
            out[(rs0 + t) * 3 + j] = sig * 1.002f - 0.001f;
        }
    }
}

// ---------------- launch ----------------
extern "C" void kernel_launch(void* const* d_in, const int* in_sizes, int n_in,
                              void* d_out, int out_size)
{
    const float* means = (const float*)d_in[0];
    const float* stds  = (const float*)d_in[1];
    const float* vd    = (const float*)d_in[2];
    const float* table = (const float*)d_in[3];
    const float* dw1   = (const float*)d_in[4];
    const float* db1   = (const float*)d_in[5];
    const float* dw2   = (const float*)d_in[6];
    const float* db2   = (const float*)d_in[7];
    const float* vw0   = (const float*)d_in[8];
    const float* vb0   = (const float*)d_in[9];
    const float* vw1   = (const float*)d_in[10];
    const float* vb1   = (const float*)d_in[11];
    const float* rw    = (const float*)d_in[12];
    const float* rb    = (const float*)d_in[13];
    float* out = (float*)d_out;

    cudaFuncSetAttribute(mlp_mma_kernel, cudaFuncAttributeMaxDynamicSharedMemorySize, SM_TOTAL);

    prep_kernel<<<(PK_TOTAL_H2 + 255) / 256, 256>>>(dw1, dw2, vw0, vw1);

    dim3 g1(RS_TOTAL / 128, NUM_LEVELS);
    grid_encode_kernel<<<g1, 128>>>(means, stds, (const float4*)table);

    mlp_mma_kernel<<<NCTA, 256, SM_TOTAL>>>(vd, db1, db2, vb0, vb1,
                                            vw0, vw1, rw, rb, out);
}

// round 10
// speedup vs baseline: 1.6023x; 1.0029x over previous
#include <cuda_runtime.h>
#include <cuda_fp16.h>
#include <math.h>
#include <stdint.h>

// ---------------- problem constants ----------------
#define R_RAYS      4096
#define S_SAMPLES   32
#define RS_TOTAL    131072
#define M_SAMPLES   6
#define NUM_LEVELS  10
#define FEAT_DIM    40
#define HASHMASK    2097151u
#define RGB_ELEMS   393216

#define ROWS_CTA    64
#define NCTA        (RS_TOTAL / ROWS_CTA)     // 2048

__constant__ int c_offsets[NUM_LEVELS] = {
    0, 4920, 40864, 315496, 2412648, 4509800, 6606952, 8704104, 10801256, 12898408
};
__constant__ int c_sizes[NUM_LEVELS] = {
    4920, 35944, 274632, 2097152, 2097152, 2097152, 2097152, 2097152, 2097152, 2097152
};

// fp16 feature scratch: [rs][40]
__device__ __half g_feat_h[RS_TOTAL * FEAT_DIM];

// packed fp16 weight fragments. Layer bases (half2):
//   L1 = 0      (1536)   KT3,  N=64
//   L2 = 1536   (8192)   KT4,  N=256
//   L3 = 9728   (32768)  KT16, N=256  (x only; dir folded into bias)
//   L4 = 42496  (65536)  KT32, N=256  (h2|x only)
#define PK_TOTAL_H2 108032
__device__ __align__(16) __half2 Wpk[PK_TOTAL_H2];

#define SLAB 568   // slab row stride in halves

// ---------------- mma helper ----------------
__device__ __forceinline__ void mma16816(float c[4],
    unsigned a0, unsigned a1, unsigned a2, unsigned a3,
    unsigned b0, unsigned b1)
{
    asm volatile(
        "mma.sync.aligned.m16n8k16.row.col.f32.f16.f16.f32 "
        "{%0,%1,%2,%3}, {%4,%5,%6,%7}, {%8,%9}, {%0,%1,%2,%3};"
        : "+f"(c[0]), "+f"(c[1]), "+f"(c[2]), "+f"(c[3])
        : "r"(a0), "r"(a1), "r"(a2), "r"(a3), "r"(b0), "r"(b1));
}

// ---------------- kernel 0: weight prep ----------------
__global__ __launch_bounds__(256) void prep_kernel(
    const float* __restrict__ dw1, const float* __restrict__ dw2,
    const float* __restrict__ vw0, const float* __restrict__ vw1)
{
    int idx = blockIdx.x * 256 + threadIdx.x;
    if (idx >= PK_TOTAL_H2) return;

    int local, NP, layer;
    if (idx < 1536)        { layer = 1; local = idx;         NP = 4;  }
    else if (idx < 9728)   { layer = 2; local = idx - 1536;  NP = 16; }
    else if (idx < 42496)  { layer = 3; local = idx - 9728;  NP = 16; }
    else                   { layer = 4; local = idx - 42496; NP = 16; }

    const int j    = local & 3;
    const int lane = (local >> 2) & 31;
    const int rem  = local >> 7;
    const int np   = rem % NP;
    const int kt   = rem / NP;

    const int nt  = np * 2 + (j >> 1);
    const int reg = j & 1;
    const int n   = nt * 8 + (lane >> 2);
    const int k   = kt * 16 + reg * 8 + (lane & 3) * 2;

    float v0 = 0.f, v1 = 0.f;
    if (layer == 1) {
        if (k     < 40) v0 = dw1[k * 64 + n];
        if (k + 1 < 40) v1 = dw1[(k + 1) * 64 + n];
    } else if (layer == 2) {
        v0 = dw2[k * 256 + n];
        v1 = dw2[(k + 1) * 256 + n];
    } else if (layer == 3) {
        v0 = vw0[k * 256 + n];
        v1 = vw0[(k + 1) * 256 + n];
    } else {
        v0 = vw1[k * 256 + n];
        v1 = vw1[(k + 1) * 256 + n];
    }
    Wpk[idx] = __floats2half2_rn(v0, v1);
}

// ---------------- kernel 1: hash-grid encode (validated R7) ----------------
__global__ __launch_bounds__(128) void grid_encode_kernel(
    const float* __restrict__ means,
    const float* __restrict__ stds,
    const float4* __restrict__ table)
{
    int rs = blockIdx.x * blockDim.x + threadIdx.x;
    int level = blockIdx.y;

    const float scale = (float)(16 << level);
    const unsigned res = (unsigned)((16 << level) + 1);
    const bool dense = (level < 3);
    const int off = c_offsets[level];
    const unsigned size_m1 = (unsigned)(c_sizes[level] - 1);

    float acc0 = 0.f, acc1 = 0.f, acc2 = 0.f, acc3 = 0.f;

    #pragma unroll
    for (int m = 0; m < M_SAMPLES; m++) {
        const int pidx = rs * M_SAMPLES + m;
        const float mx = means[pidx * 3 + 0];
        const float my = means[pidx * 3 + 1];
        const float mz = means[pidx * 3 + 2];
        const float sd = stds[pidx];
        const float wl = erff(1.0f / (2.8284271247461903f * sd * scale));

        float px = (mx + 1.0f) * 0.5f * scale + 0.5f;
        float py = (my + 1.0f) * 0.5f * scale + 0.5f;
        float pz = (mz + 1.0f) * 0.5f * scale + 0.5f;
        float f0x = floorf(px), f0y = floorf(py), f0z = floorf(pz);
        float fx = px - f0x, fy = py - f0y, fz = pz - f0z;
        unsigned ux = (unsigned)f0x, uy = (unsigned)f0y, uz = (unsigned)f0z;

        #pragma unroll
        for (int c = 0; c < 8; c++) {
            const unsigned bx = c & 1u, by = (c >> 1) & 1u, bz = (c >> 2) & 1u;
            const unsigned cx = ux + bx, cy = uy + by, cz = uz + bz;
            unsigned idx;
            if (dense) { idx = (cx * res + cy) * res + cz; idx = min(idx, size_m1); }
            else { idx = (cx * 1u) ^ (cy * 2654435761u) ^ (cz * 805459861u); idx &= HASHMASK; }
            const float wx = bx ? fx : (1.0f - fx);
            const float wy = by ? fy : (1.0f - fy);
            const float wz = bz ? fz : (1.0f - fz);
            const float w = wx * wy * wz * wl;
            const float4 tt = __ldg(table + off + (int)idx);
            acc0 += w * tt.x; acc1 += w * tt.y; acc2 += w * tt.z; acc3 += w * tt.w;
        }
    }
    const float inv = 1.0f / 6.0f;
    __half2 lo = __floats2half2_rn(acc0 * inv, acc1 * inv);
    __half2 hi = __floats2half2_rn(acc2 * inv, acc3 * inv);
    *(__half2*)&g_feat_h[rs * FEAT_DIM + level * 4]     = lo;
    *(__half2*)&g_feat_h[rs * FEAT_DIM + level * 4 + 2] = hi;
}

// ---------------- L1 fragment-GEMM (R9 mapping): warp = 2 m-tiles x 2 n-tiles ----------------
template<int KT, int NTW, int NP>
__device__ __forceinline__ void run_layer2(
    const __half* slab, int acol0, int mp, int gr, int gc,
    const __half2* __restrict__ wpk, int nq, int lane, float C[2][NTW][4])
{
    const __half* arow0 = slab + (mp * 32 + gr) * SLAB + acol0 + gc * 2;
    const uint4* wbase = (const uint4*)wpk + (size_t)(nq * (NTW / 2)) * 32 + lane;
    #pragma unroll 1
    for (int kt = 0; kt < KT; kt++) {
        const __half* ap0 = arow0 + kt * 16;
        const __half* ap1 = ap0 + 16 * SLAB;
        unsigned a0 = *(const unsigned*)(ap0);
        unsigned a2 = *(const unsigned*)(ap0 + 8);
        unsigned a1 = *(const unsigned*)(ap0 + 8 * SLAB);
        unsigned a3 = *(const unsigned*)(ap0 + 8 * SLAB + 8);
        unsigned a4 = *(const unsigned*)(ap1);
        unsigned a6 = *(const unsigned*)(ap1 + 8);
        unsigned a5 = *(const unsigned*)(ap1 + 8 * SLAB);
        unsigned a7 = *(const unsigned*)(ap1 + 8 * SLAB + 8);
        const uint4* wp = wbase + (size_t)kt * NP * 32;
        #pragma unroll
        for (int p = 0; p < NTW / 2; p++) {
            uint4 b = __ldg(wp + p * 32);
            mma16816(C[0][2 * p],     a0, a1, a2, a3, b.x, b.y);
            mma16816(C[0][2 * p + 1], a0, a1, a2, a3, b.z, b.w);
            mma16816(C[1][2 * p],     a4, a5, a6, a7, b.x, b.y);
            mma16816(C[1][2 * p + 1], a4, a5, a6, a7, b.z, b.w);
        }
    }
}

// ---------------- L2-L4 fragment-GEMM: warp = 4 m-tiles (all 64 rows) x 4 n-tiles ----------
// B double-buffered: kt+1's two uint4 prefetched while kt's 16 mma issue.
template<int KT>
__device__ __forceinline__ void run_layer4(
    const __half* slab, int acol0, int gr, int gc,
    const __half2* __restrict__ wpk, int nq, int lane, float C[4][4][4])
{
    const __half* arow = slab + gr * SLAB + acol0 + gc * 2;
    const uint4* wbase = (const uint4*)wpk + (size_t)(nq * 2) * 32 + lane;
    uint4 b0 = __ldg(wbase);
    uint4 b1 = __ldg(wbase + 32);
    #pragma unroll 1
    for (int kt = 0; kt < KT; kt++) {
        const uint4 cur0 = b0, cur1 = b1;
        if (kt + 1 < KT) {
            const uint4* wp = wbase + (size_t)(kt + 1) * 16 * 32;
            b0 = __ldg(wp);
            b1 = __ldg(wp + 32);
        }
        #pragma unroll
        for (int m = 0; m < 4; m++) {
            const __half* ap = arow + m * 16 * SLAB + kt * 16;
            unsigned a0 = *(const unsigned*)(ap);
            unsigned a2 = *(const unsigned*)(ap + 8);
            unsigned a1 = *(const unsigned*)(ap + 8 * SLAB);
            unsigned a3 = *(const unsigned*)(ap + 8 * SLAB + 8);
            mma16816(C[m][0], a0, a1, a2, a3, cur0.x, cur0.y);
            mma16816(C[m][1], a0, a1, a2, a3, cur0.z, cur0.w);
            mma16816(C[m][2], a0, a1, a2, a3, cur1.x, cur1.y);
            mma16816(C[m][3], a0, a1, a2, a3, cur1.z, cur1.w);
        }
    }
}

// ---------------- kernel 2: MLP, 64 rows/CTA, occ 2, full-M warps + B prefetch ----------
// smem: slab 64x568 halves (72704B) | dirsm 64f | d3s 512f | d4s 512f | rwsm 768f | parth 1536f
#define SM_DIR   72704
#define SM_D3    72960
#define SM_D4    75008
#define SM_RW    77056
#define SM_PARTH 80128
#define SM_TOTAL 86272

__global__ __launch_bounds__(256, 2) void mlp_mma_kernel(
    const float* __restrict__ vd,
    const float* __restrict__ db1, const float* __restrict__ db2,
    const float* __restrict__ vb0, const float* __restrict__ vb1,
    const float* __restrict__ vw0, const float* __restrict__ vw1,
    const float* __restrict__ rw,  const float* __restrict__ rbias,
    float* __restrict__ out)
{
    extern __shared__ char dyn[];
    __half* slab = (__half*)dyn;
    float* dirsm = (float*)(dyn + SM_DIR);
    float* d3s   = (float*)(dyn + SM_D3);
    float* d4s   = (float*)(dyn + SM_D4);
    float* rwsm  = (float*)(dyn + SM_RW);
    float* parth = (float*)(dyn + SM_PARTH);

    const int t = threadIdx.x;
    const int w = t >> 5, lane = t & 31;
    const int gr = lane >> 2, gc = lane & 3;
    const int rs0 = blockIdx.x * ROWS_CTA;

    // rw -> smem
    for (int i = t; i < 768; i += 256) rwsm[i] = rw[i];

    // dir encoding: 2 rays x 32 cols (cols >= 27 zero)
    if (t < 64) {
        int rayi = t >> 5, c = t & 31;
        int rg = blockIdx.x * 2 + rayi;
        float v = 0.f;
        if (c < 3) v = vd[rg * 3 + c];
        else if (c < 15) { int j = c - 3;  v = sinf(vd[rg * 3 + (j % 3)] * (float)(1 << (j / 3))); }
        else if (c < 27) { int j = c - 15; v = cosf(vd[rg * 3 + (j % 3)] * (float)(1 << (j / 3))); }
        dirsm[t] = v;
        // zero feat pad cols 40..47
        *(uint4*)&slab[t * SLAB + 40] = make_uint4(0, 0, 0, 0);
    }

    // feat (fp16) -> slab cols 0..39
    #pragma unroll
    for (int i = t; i < ROWS_CTA * 20; i += 256) {
        int r = i / 20, c = i % 20;
        *(unsigned*)&slab[r * SLAB + c * 2] =
            *(const unsigned*)&g_feat_h[(rs0 + r) * FEAT_DIM + c * 2];
    }
    __syncthreads();

    // dir contribution folded to per-(ray,channel) scalars (fp32)
    {
        const int ry = t >> 7;
        const int ch = (t & 127) * 2;
        const float* dv = &dirsm[ry * 32];
        float a3 = 0.f, b3 = 0.f, a4 = 0.f, b4 = 0.f;
        #pragma unroll
        for (int j = 0; j < 27; j++) {
            const float d = dv[j];
            const float2 w3 = *(const float2*)&vw0[(256 + j) * 256 + ch];
            const float2 w4 = *(const float2*)&vw1[(512 + j) * 256 + ch];
            a3 += d * w3.x; b3 += d * w3.y;
            a4 += d * w4.x; b4 += d * w4.y;
        }
        *(float2*)&d3s[ry * 256 + ch] = make_float2(a3, b3);
        *(float2*)&d4s[ry * 256 + ch] = make_float2(a4, b4);
    }
    __syncthreads();

    // ---- L1: feat(cols 0..47) @ W1 -> h1 (relu) -> cols 64..127 (R9 mapping) ----
    {
        const int mp = w & 1, nq = w >> 1;
        float C[2][2][4] = {};
        run_layer2<3, 2, 4>(slab, 0, mp, gr, gc, Wpk, nq, lane, C);
        #pragma unroll
        for (int mm = 0; mm < 2; mm++) {
            const int r0 = mp * 32 + mm * 16 + gr;
            #pragma unroll
            for (int nt = 0; nt < 2; nt++) {
                int n = nq * 16 + nt * 8 + 2 * gc;
                float2 b = *(const float2*)&db1[n];
                __half2 lo = __floats2half2_rn(fmaxf(C[mm][nt][0] + b.x, 0.f), fmaxf(C[mm][nt][1] + b.y, 0.f));
                __half2 hi = __floats2half2_rn(fmaxf(C[mm][nt][2] + b.x, 0.f), fmaxf(C[mm][nt][3] + b.y, 0.f));
                *(__half2*)&slab[r0 * SLAB + 64 + n]       = lo;
                *(__half2*)&slab[(r0 + 8) * SLAB + 64 + n] = hi;
            }
        }
    }
    __syncthreads();

    // ---- L2: h1(cols 64..127) @ W2 -> x (cols 256..511); density ----
    {
        float C[4][4][4] = {};
        run_layer4<4>(slab, 64, gr, gc, Wpk + 1536, w, lane, C);
        #pragma unroll
        for (int m = 0; m < 4; m++) {
            const int r0 = m * 16 + gr;
            if (w == 0 && gc == 0) {
                float xa = C[m][0][0] + __ldg(&db2[0]) - 1.0f;
                float xb = C[m][0][2] + __ldg(&db2[0]) - 1.0f;
                out[RGB_ELEMS + rs0 + r0]     = fmaxf(xa, 0.f) + log1pf(expf(-fabsf(xa)));
                out[RGB_ELEMS + rs0 + r0 + 8] = fmaxf(xb, 0.f) + log1pf(expf(-fabsf(xb)));
            }
            #pragma unroll
            for (int nt = 0; nt < 4; nt++) {
                int n = w * 32 + nt * 8 + 2 * gc;
                float2 b = *(const float2*)&db2[n];
                __half2 lo = __floats2half2_rn(C[m][nt][0] + b.x, C[m][nt][1] + b.y);
                __half2 hi = __floats2half2_rn(C[m][nt][2] + b.x, C[m][nt][3] + b.y);
                *(__half2*)&slab[r0 * SLAB + 256 + n]       = lo;
                *(__half2*)&slab[(r0 + 8) * SLAB + 256 + n] = hi;
            }
        }
    }
    __syncthreads();

    // ---- L3: x(cols 256..511) @ W3 + dirfold -> h2 (relu) -> cols 0..255 ----
    {
        float C[4][4][4] = {};
        run_layer4<16>(slab, 256, gr, gc, Wpk + 9728, w, lane, C);
        #pragma unroll
        for (int m = 0; m < 4; m++) {
            const int r0 = m * 16 + gr;
            const int ry = m >> 1;
            #pragma unroll
            for (int nt = 0; nt < 4; nt++) {
                int n = w * 32 + nt * 8 + 2 * gc;
                float2 b = *(const float2*)&vb0[n];
                float2 d = *(const float2*)&d3s[ry * 256 + n];
                float b0 = b.x + d.x, b1 = b.y + d.y;
                __half2 lo = __floats2half2_rn(fmaxf(C[m][nt][0] + b0, 0.f), fmaxf(C[m][nt][1] + b1, 0.f));
                __half2 hi = __floats2half2_rn(fmaxf(C[m][nt][2] + b0, 0.f), fmaxf(C[m][nt][3] + b1, 0.f));
                *(__half2*)&slab[r0 * SLAB + n]       = lo;
                *(__half2*)&slab[(r0 + 8) * SLAB + n] = hi;
            }
        }
    }
    __syncthreads();

    // ---- L4: [h2|x](cols 0..511) @ W4 + dirfold -> h3 (regs) -> rgb head ----
    {
        float C[4][4][4] = {};
        run_layer4<32>(slab, 0, gr, gc, Wpk + 42496, w, lane, C);

        #pragma unroll
        for (int m = 0; m < 4; m++) {
            const int r0 = m * 16 + gr;
            const int ry = m >> 1;
            float pl[3] = {0.f, 0.f, 0.f}, ph[3] = {0.f, 0.f, 0.f};
            #pragma unroll
            for (int nt = 0; nt < 4; nt++) {
                int n = w * 32 + nt * 8 + 2 * gc;
                float2 b = *(const float2*)&vb1[n];
                float2 d = *(const float2*)&d4s[ry * 256 + n];
                float b0 = b.x + d.x, b1 = b.y + d.y;
                float h0 = fmaxf(C[m][nt][0] + b0, 0.f);
                float h1 = fmaxf(C[m][nt][1] + b1, 0.f);
                float h2 = fmaxf(C[m][nt][2] + b0, 0.f);
                float h3 = fmaxf(C[m][nt][3] + b1, 0.f);
                #pragma unroll
                for (int j = 0; j < 3; j++) {
                    pl[j] += h0 * rwsm[n * 3 + j] + h1 * rwsm[(n + 1) * 3 + j];
                    ph[j] += h2 * rwsm[n * 3 + j] + h3 * rwsm[(n + 1) * 3 + j];
                }
            }
            #pragma unroll
            for (int j = 0; j < 3; j++) {
                pl[j] += __shfl_xor_sync(0xffffffffu, pl[j], 1);
                pl[j] += __shfl_xor_sync(0xffffffffu, pl[j], 2);
                ph[j] += __shfl_xor_sync(0xffffffffu, ph[j], 1);
                ph[j] += __shfl_xor_sync(0xffffffffu, ph[j], 2);
            }
            if (gc == 0) {
                #pragma unroll
                for (int j = 0; j < 3; j++) {
                    parth[r0 * 24 + w * 3 + j]       = pl[j];
                    parth[(r0 + 8) * 24 + w * 3 + j] = ph[j];
                }
            }
        }
    }
    __syncthreads();

    if (t < ROWS_CTA) {
        #pragma unroll
        for (int j = 0; j < 3; j++) {
            float s = __ldg(&rbias[j]);
            #pragma unroll
            for (int q = 0; q < 8; q++) s += parth[t * 24 + q * 3 + j];
            float sig = 1.0f / (1.0f + expf(-s));
            out[(rs0 + t) * 3 + j] = sig * 1.002f - 0.001f;
        }
    }
}

// ---------------- launch ----------------
extern "C" void kernel_launch(void* const* d_in, const int* in_sizes, int n_in,
                              void* d_out, int out_size)
{
    const float* means = (const float*)d_in[0];
    const float* stds  = (const float*)d_in[1];
    const float* vd    = (const float*)d_in[2];
    const float* table = (const float*)d_in[3];
    const float* dw1   = (const float*)d_in[4];
    const float* db1   = (const float*)d_in[5];
    const float* dw2   = (const float*)d_in[6];
    const float* db2   = (const float*)d_in[7];
    const float* vw0   = (const float*)d_in[8];
    const float* vb0   = (const float*)d_in[9];
    const float* vw1   = (const float*)d_in[10];
    const float* vb1   = (const float*)d_in[11];
    const float* rw    = (const float*)d_in[12];
    const float* rb    = (const float*)d_in[13];
    float* out = (float*)d_out;

    cudaFuncSetAttribute(mlp_mma_kernel, cudaFuncAttributeMaxDynamicSharedMemorySize, SM_TOTAL);

    prep_kernel<<<(PK_TOTAL_H2 + 255) / 256, 256>>>(dw1, dw2, vw0, vw1);

    dim3 g1(RS_TOTAL / 128, NUM_LEVELS);
    grid_encode_kernel<<<g1, 128>>>(means, stds, (const float4*)table);

    mlp_mma_kernel<<<NCTA, 256, SM_TOTAL>>>(vd, db1, db2, vb0, vb1,
                                            vw0, vw1, rw, rb, out);
}